// round 11
// baseline (speedup 1.0000x reference)
#include <cuda_runtime.h>
#include <cuda_bf16.h>
#include <stdint.h>

// ---------------- problem constants (fixed shapes) ----------------
#define DD   128
#define HH   192
#define WP   193            // pred_z last-dim
#define WW   192            // d last-dim (WP-1)
#define TOTD (DD*HH*WW)     // 4,718,592
#define N0   (DD*HH)        // 24,576 first-slice elements
#define RANK ((N0-1)/2)     // 12,287 (lower median, 0-based)

// ---------------- device scratch (no allocations allowed) ----------------
__device__ double   g_sum;              // sum of (d-med)^2
__device__ unsigned g_mon;              // float bits of max(relu(1-dz))
__device__ int      g_hist[1024];       // radix histogram (top 10 bits of key)
__device__ unsigned g_z0[N0];           // staged sortable keys of first-slice values
__device__ unsigned g_cand[N0];         // candidate keys
__device__ int      g_ccount;

// ---------------- helpers ----------------
__device__ __forceinline__ int refl(int i, int n) {
    return (i < 0) ? -i : ((i >= n) ? (2*n - 2 - i) : i);
}

__device__ __forceinline__ unsigned f2key(float f) {
    unsigned u = __float_as_uint(f);
    return (u & 0x80000000u) ? ~u : (u | 0x80000000u);
}
__device__ __forceinline__ float key2f(unsigned k) {
    unsigned u = (k & 0x80000000u) ? (k & 0x7fffffffu) : ~k;
    return __uint_as_float(u);
}

__device__ __forceinline__ void ce(float& a, float& b) {
    float mn = fminf(a, b);
    float mx = fmaxf(a, b);
    a = mn; b = mx;
}

// ---------- sorting / merging networks (Batcher odd-even) ----------
__device__ __forceinline__ void sort3(float&a,float&b,float&c){ ce(a,b); ce(a,c); ce(b,c); }
__device__ __forceinline__ void sort4(float&a,float&b,float&c,float&d){
    ce(a,b); ce(c,d); ce(a,c); ce(b,d); ce(b,c);
}
__device__ __forceinline__ void merge12(float a0,float b0,float b1,float z[3]){
    float v0=fminf(a0,b0), v1=fmaxf(a0,b0);
    z[0]=v0; z[1]=fminf(b1,v1); z[2]=fmaxf(b1,v1);
}
__device__ __forceinline__ void merge22(float a0,float a1,float b0,float b1,float z[4]){
    float v0=fminf(a0,b0), v1=fmaxf(a0,b0);
    float w0=fminf(a1,b1), w1=fmaxf(a1,b1);
    z[0]=v0; z[1]=fminf(w0,v1); z[2]=fmaxf(w0,v1); z[3]=w1;
}
__device__ __forceinline__ void merge23(float a0,float a1,float b0,float b1,float b2,float z[5]){
    float v[3]; merge12(a0,b0,b2,v);
    float w0=fminf(a1,b1), w1=fmaxf(a1,b1);
    z[0]=v[0];
    z[1]=fminf(w0,v[1]); z[2]=fmaxf(w0,v[1]);
    z[3]=fminf(w1,v[2]); z[4]=fmaxf(w1,v[2]);
}
__device__ __forceinline__ void merge33(float a0,float a1,float a2,float b0,float b1,float b2,float z[6]){
    float v[4]; merge22(a0,a2,b0,b2,v);
    float w0=fminf(a1,b1), w1=fmaxf(a1,b1);
    z[0]=v[0];
    z[1]=fminf(w0,v[1]); z[2]=fmaxf(w0,v[1]);
    z[3]=fminf(w1,v[2]); z[4]=fmaxf(w1,v[2]);
    z[5]=v[3];
}
__device__ __forceinline__ void merge44(float a0,float a1,float a2,float a3,
                                        float b0,float b1,float b2,float b3,float z[8]){
    float v[4]; merge22(a0,a2,b0,b2,v);
    float w[4]; merge22(a1,a3,b1,b3,w);
    z[0]=v[0];
    z[1]=fminf(w[0],v[1]); z[2]=fmaxf(w[0],v[1]);
    z[3]=fminf(w[1],v[2]); z[4]=fmaxf(w[1],v[2]);
    z[5]=fminf(w[2],v[3]); z[6]=fmaxf(w[2],v[3]);
    z[7]=w[3];
}
__device__ __forceinline__ void merge45(float a0,float a1,float a2,float a3,
                                        float b0,float b1,float b2,float b3,float b4,float z[9]){
    float v[5]; merge23(a0,a2,b0,b2,b4,v);
    float w[4]; merge22(a1,a3,b1,b3,w);
    z[0]=v[0];
    z[1]=fminf(w[0],v[1]); z[2]=fmaxf(w[0],v[1]);
    z[3]=fminf(w[1],v[2]); z[4]=fmaxf(w[1],v[2]);
    z[5]=fminf(w[2],v[3]); z[6]=fmaxf(w[2],v[3]);
    z[7]=fminf(w[3],v[4]); z[8]=fmaxf(w[3],v[4]);
}
__device__ __forceinline__ void merge55(float a0,float a1,float a2,float a3,float a4,
                                        float b0,float b1,float b2,float b3,float b4,float z[10]){
    float v[6]; merge33(a0,a2,a4,b0,b2,b4,v);
    float w[4]; merge22(a1,a3,b1,b3,w);
    z[0]=v[0];
    z[1]=fminf(w[0],v[1]); z[2]=fmaxf(w[0],v[1]);
    z[3]=fminf(w[1],v[2]); z[4]=fmaxf(w[1],v[2]);
    z[5]=fminf(w[2],v[3]); z[6]=fmaxf(w[2],v[3]);
    z[7]=fminf(w[3],v[4]); z[8]=fmaxf(w[3],v[4]);
    z[9]=v[5];
}

// in-place sort of 9 (odd-even mergesort: 26 CE)
__device__ __forceinline__ void sort9(float p[9]){
    sort4(p[0],p[1],p[2],p[3]);
    ce(p[4],p[5]);
    sort3(p[6],p[7],p[8]);
    { float q[5]; merge23(p[4],p[5],p[6],p[7],p[8],q);
      p[4]=q[0]; p[5]=q[1]; p[6]=q[2]; p[7]=q[3]; p[8]=q[4]; }
    float s[9]; merge45(p[0],p[1],p[2],p[3],p[4],p[5],p[6],p[7],p[8],s);
#pragma unroll
    for(int i=0;i<9;i++) p[i]=s[i];
}

// middle outputs z[4..13] of odd-even merge(9,9) of sorted A, B  -> mid[0..9]
__device__ __forceinline__ void merge99_mid(const float A[9], const float B[9], float mid[10]){
    float v[10], w[8];
    merge55(A[0],A[2],A[4],A[6],A[8], B[0],B[2],B[4],B[6],B[8], v);
    merge44(A[1],A[3],A[5],A[7],      B[1],B[3],B[5],B[7],      w);
    mid[0]=fmaxf(w[1],v[2]);                          // z4
    mid[1]=fminf(w[2],v[3]); mid[2]=fmaxf(w[2],v[3]); // z5,z6
    mid[3]=fminf(w[3],v[4]); mid[4]=fmaxf(w[3],v[4]); // z7,z8
    mid[5]=fminf(w[4],v[5]); mid[6]=fmaxf(w[4],v[5]); // z9,z10
    mid[7]=fminf(w[5],v[6]); mid[8]=fmaxf(w[5],v[6]); // z11,z12
    mid[9]=fminf(w[6],v[7]);                          // z13
}

// rank-13 (0-based) of 27 = 14th smallest of sorted-18 (mid=z[4..13]) u sorted-9 C
__device__ __forceinline__ float select13(const float mid[10], const float C[9]){
    float t0 = fminf(fmaxf(mid[0],C[8]), fmaxf(mid[1],C[7]));
    float t1 = fminf(fmaxf(mid[2],C[6]), fmaxf(mid[3],C[5]));
    float t2 = fminf(fmaxf(mid[4],C[4]), fmaxf(mid[5],C[3]));
    float t3 = fminf(fmaxf(mid[6],C[2]), fmaxf(mid[7],C[1]));
    float t4 = fminf(fmaxf(mid[8],C[0]), mid[9]);
    return fminf(fminf(fminf(t0,t1), fminf(t2,t3)), t4);
}

// ---------------- median kernel (fused diff + mon + median + hist + residual sum) ------
// Each thread processes TWO x-adjacent voxels with independent scalar chains (ILP x2).
#define TXV 16              // threads in x
#define TX  (2*TXV)         // voxels in x per block (32)
#define TY  8               // voxels in y per block
#define ZC  32              // z-planes per block
#define PITCH (TX+3)        // 35
__global__ __launch_bounds__(TXV*TY, 4) void k_median(const float* __restrict__ p){
    __shared__ float sm[2][(TY+2)*PITCH];
    const int tx  = threadIdx.x;           // 0..15
    const int ty  = threadIdx.y;           // 0..7
    const int tid = ty*TXV + tx;           // 0..127
    const int gx0 = blockIdx.x*TX;
    const int gy0 = blockIdx.y*TY;
    const int z0  = blockIdx.z*ZC;

    // ---- fused first-slice key staging + histogram (first 192 blocks) ----
    {
        int b = blockIdx.x + 6*(blockIdx.y + 24*blockIdx.z);
        if (b < 192){
            int i = b*128 + tid;                       // covers N0 exactly
            unsigned key = f2key(p[(size_t)i * WP]);
            g_z0[i] = key;
            atomicAdd(&g_hist[key >> 22], 1);
        }
    }

    // stage one z-plane of d (reflect in y,x) into smem buffer `buf`
    auto load_plane = [&](int z, int buf){
        const int zr = refl(z, DD);
        const float* base = p + (size_t)zr * HH * WP;
        for (int idx = tid; idx < (TY+2)*(TX+2); idx += TXV*TY){
            int yy = idx/(TX+2), xx = idx%(TX+2);
            int gy = refl(gy0-1+yy, HH);
            int gx = refl(gx0-1+xx, WW);
            const float* r = base + (size_t)gy*WP + gx;
            sm[buf][yy*PITCH + xx] = r[1] - r[0];
        }
    };
    // read 3x3 neighborhoods for voxels x=2tx and 2tx+1 (4 LDS per row, shared)
    auto read9_2 = [&](int buf, float q0[9], float q1[9], float& c0, float& c1){
#pragma unroll
        for (int jr = 0; jr < 3; jr++){
            const float* rp = &sm[buf][(ty+jr)*PITCH + 2*tx];
            float s0 = rp[0], s1 = rp[1], s2 = rp[2], s3 = rp[3];
            q0[3*jr+0] = s0; q0[3*jr+1] = s1; q0[3*jr+2] = s2;
            q1[3*jr+0] = s1; q1[3*jr+1] = s2; q1[3*jr+2] = s3;
        }
        c0 = q0[4]; c1 = q1[4];
    };

    float A0[9], A1[9], B0[9], B1[9], M0[10], M1[10];
    float cA0, cA1, cB0, cB1, d0, d1;

    // prologue: plane z0-1 -> A (sorted), plane z0 -> B (sorted) + centers
    load_plane(z0-1, 0); __syncthreads(); read9_2(0, A0, A1, d0, d1);
    sort9(A0); sort9(A1);
    load_plane(z0,   1); __syncthreads(); read9_2(1, B0, B1, cB0, cB1);
    sort9(B0); sort9(B1);
    merge99_mid(A0, B0, M0);
    merge99_mid(A1, B1, M1);

    float lsum = 0.0f, lmax = 0.0f;
#pragma unroll 1
    for (int zi = 0; zi < ZC; zi += 2){
        const int z = z0 + zi;
        // window {z-1,z,z+1}: M=merge(z-1,z), C=sorted plane z+1, centers from plane z
        load_plane(z+1, 0); __syncthreads(); read9_2(0, A0, A1, cA0, cA1);
        sort9(A0); sort9(A1);
        {
            float m0 = select13(M0, A0);
            float m1 = select13(M1, A1);
            float e0 = cB0 - m0, e1 = cB1 - m1;
            lsum += e0*e0 + e1*e1;
            lmax  = fmaxf(lmax, fmaxf(1.0f - cB0, 1.0f - cB1));
        }
        merge99_mid(B0, A0, M0);
        merge99_mid(B1, A1, M1);

        // window {z,z+1,z+2}: centers from plane z+1
        load_plane(z+2, 1); __syncthreads(); read9_2(1, B0, B1, cB0, cB1);
        sort9(B0); sort9(B1);
        {
            float m0 = select13(M0, B0);
            float m1 = select13(M1, B1);
            float e0 = cA0 - m0, e1 = cA1 - m1;
            lsum += e0*e0 + e1*e1;
            lmax  = fmaxf(lmax, fmaxf(1.0f - cA0, 1.0f - cA1));
        }
        merge99_mid(A0, B0, M0);
        merge99_mid(A1, B1, M1);
    }

    // block reduction
#pragma unroll
    for (int off = 16; off; off >>= 1){
        lsum += __shfl_xor_sync(0xffffffffu, lsum, off);
        lmax  = fmaxf(lmax, __shfl_xor_sync(0xffffffffu, lmax, off));
    }
    __shared__ float rs[4], rm[4];
    if ((tid & 31) == 0){ rs[tid>>5] = lsum; rm[tid>>5] = lmax; }
    __syncthreads();
    if (tid == 0){
        float s = rs[0]+rs[1]+rs[2]+rs[3];
        float m = fmaxf(fmaxf(rm[0], rm[1]), fmaxf(rm[2], rm[3]));
        atomicAdd(&g_sum, (double)s);
        atomicMax(&g_mon, __float_as_uint(m));   // m >= 0 always (lmax init 0)
    }
}

// ---------------- scan + gather + select + finalize + reset (single block) --------------
__global__ void k_post(float* __restrict__ out){
    __shared__ int s[1024];
    __shared__ int sb[2];
    const int t = threadIdx.x;

    int h = g_hist[t];
    s[t] = h;
    __syncthreads();
    for (int off = 1; off < 1024; off <<= 1){
        int v = (t >= off) ? s[t-off] : 0;
        __syncthreads();
        s[t] += v;
        __syncthreads();
    }
    int incl = s[t], excl = incl - h;
    if (excl <= RANK && RANK < incl){ sb[0] = t; sb[1] = RANK - excl; }
    __syncthreads();
    const int bkt = sb[0];

    for (int i = t; i < N0; i += 1024){
        unsigned key = g_z0[i];
        if ((int)(key >> 22) == bkt){
            int pos = atomicAdd(&g_ccount, 1);
            g_cand[pos] = key;
        }
    }
    __syncthreads();
    const int m = g_ccount;
    const int r = sb[1];
    for (int i = t; i < m; i += 1024){
        unsigned ki = g_cand[i];
        int less = 0, eq = 0;
        for (int j = 0; j < m; j++){
            unsigned kj = g_cand[j];
            less += (kj < ki);
            eq   += (kj == ki);
        }
        if (less <= r && r < less + eq){
            float v = key2f(ki);
            out[2] = v*v;                         // loss_average
        }
    }
    __syncthreads();
    if (t == 0){
        out[0] = (float)(g_sum * (1.0/(double)TOTD));  // loss_smooth
        out[1] = __uint_as_float(g_mon);               // loss_mon
        g_sum = 0.0; g_mon = 0u; g_ccount = 0;         // reset for next replay
    }
    g_hist[t] = 0;
}

// ---------------- launch ----------------
extern "C" void kernel_launch(void* const* d_in, const int* in_sizes, int n_in,
                              void* d_out, int out_size) {
    const float* p = (const float*)d_in[0];
    float* out = (float*)d_out;

    {
        dim3 grid(WW/TX, HH/TY, DD/ZC);   // 6 x 24 x 4 = 576 blocks (single wave @4/SM)
        dim3 block(TXV, TY);              // 128 threads
        k_median<<<grid, block>>>(p);
    }
    k_post<<<1, 1024>>>(out);
}

// round 12
// speedup vs baseline: 1.2644x; 1.2644x over previous
#include <cuda_runtime.h>
#include <cuda_bf16.h>
#include <stdint.h>

// ---------------- problem constants (fixed shapes) ----------------
#define DD   128
#define HH   192
#define WP   193            // pred_z last-dim
#define WW   192            // d last-dim (WP-1)
#define TOTD (DD*HH*WW)     // 4,718,592
#define N0   (DD*HH)        // 24,576 first-slice elements
#define RANK ((N0-1)/2)     // 12,287 (lower median, 0-based)

// ---------------- device scratch (no allocations allowed) ----------------
__device__ double   g_sum;              // sum of (d-med)^2
__device__ unsigned g_mon;              // float bits of max(relu(1-dz))
__device__ int      g_hist[1024];       // radix histogram (top 10 bits of key)
__device__ unsigned g_z0[N0];           // staged sortable keys of first-slice values
__device__ unsigned g_cand[N0];         // candidate keys
__device__ int      g_ccount;

// ---------------- helpers ----------------
__device__ __forceinline__ int refl(int i, int n) {
    return (i < 0) ? -i : ((i >= n) ? (2*n - 2 - i) : i);
}

__device__ __forceinline__ unsigned f2key(float f) {
    unsigned u = __float_as_uint(f);
    return (u & 0x80000000u) ? ~u : (u | 0x80000000u);
}
__device__ __forceinline__ float key2f(unsigned k) {
    unsigned u = (k & 0x80000000u) ? (k & 0x7fffffffu) : ~k;
    return __uint_as_float(u);
}

__device__ __forceinline__ void ce(float& a, float& b) {
    float mn = fminf(a, b);
    float mx = fmaxf(a, b);
    a = mn; b = mx;
}

// ---------- sorting / merging networks (Batcher odd-even) ----------
__device__ __forceinline__ void sort3(float&a,float&b,float&c){ ce(a,b); ce(a,c); ce(b,c); }
__device__ __forceinline__ void sort4(float&a,float&b,float&c,float&d){
    ce(a,b); ce(c,d); ce(a,c); ce(b,d); ce(b,c);
}
__device__ __forceinline__ void merge12(float a0,float b0,float b1,float z[3]){
    float v0=fminf(a0,b0), v1=fmaxf(a0,b0);
    z[0]=v0; z[1]=fminf(b1,v1); z[2]=fmaxf(b1,v1);
}
__device__ __forceinline__ void merge22(float a0,float a1,float b0,float b1,float z[4]){
    float v0=fminf(a0,b0), v1=fmaxf(a0,b0);
    float w0=fminf(a1,b1), w1=fmaxf(a1,b1);
    z[0]=v0; z[1]=fminf(w0,v1); z[2]=fmaxf(w0,v1); z[3]=w1;
}
__device__ __forceinline__ void merge23(float a0,float a1,float b0,float b1,float b2,float z[5]){
    float v[3]; merge12(a0,b0,b2,v);
    float w0=fminf(a1,b1), w1=fmaxf(a1,b1);
    z[0]=v[0];
    z[1]=fminf(w0,v[1]); z[2]=fmaxf(w0,v[1]);
    z[3]=fminf(w1,v[2]); z[4]=fmaxf(w1,v[2]);
}
__device__ __forceinline__ void merge33(float a0,float a1,float a2,float b0,float b1,float b2,float z[6]){
    float v[4]; merge22(a0,a2,b0,b2,v);
    float w0=fminf(a1,b1), w1=fmaxf(a1,b1);
    z[0]=v[0];
    z[1]=fminf(w0,v[1]); z[2]=fmaxf(w0,v[1]);
    z[3]=fminf(w1,v[2]); z[4]=fmaxf(w1,v[2]);
    z[5]=v[3];
}
__device__ __forceinline__ void merge44(float a0,float a1,float a2,float a3,
                                        float b0,float b1,float b2,float b3,float z[8]){
    float v[4]; merge22(a0,a2,b0,b2,v);
    float w[4]; merge22(a1,a3,b1,b3,w);
    z[0]=v[0];
    z[1]=fminf(w[0],v[1]); z[2]=fmaxf(w[0],v[1]);
    z[3]=fminf(w[1],v[2]); z[4]=fmaxf(w[1],v[2]);
    z[5]=fminf(w[2],v[3]); z[6]=fmaxf(w[2],v[3]);
    z[7]=w[3];
}
__device__ __forceinline__ void merge45(float a0,float a1,float a2,float a3,
                                        float b0,float b1,float b2,float b3,float b4,float z[9]){
    float v[5]; merge23(a0,a2,b0,b2,b4,v);
    float w[4]; merge22(a1,a3,b1,b3,w);
    z[0]=v[0];
    z[1]=fminf(w[0],v[1]); z[2]=fmaxf(w[0],v[1]);
    z[3]=fminf(w[1],v[2]); z[4]=fmaxf(w[1],v[2]);
    z[5]=fminf(w[2],v[3]); z[6]=fmaxf(w[2],v[3]);
    z[7]=fminf(w[3],v[4]); z[8]=fmaxf(w[3],v[4]);
}
__device__ __forceinline__ void merge55(float a0,float a1,float a2,float a3,float a4,
                                        float b0,float b1,float b2,float b3,float b4,float z[10]){
    float v[6]; merge33(a0,a2,a4,b0,b2,b4,v);
    float w[4]; merge22(a1,a3,b1,b3,w);
    z[0]=v[0];
    z[1]=fminf(w[0],v[1]); z[2]=fmaxf(w[0],v[1]);
    z[3]=fminf(w[1],v[2]); z[4]=fmaxf(w[1],v[2]);
    z[5]=fminf(w[2],v[3]); z[6]=fmaxf(w[2],v[3]);
    z[7]=fminf(w[3],v[4]); z[8]=fmaxf(w[3],v[4]);
    z[9]=v[5];
}

// in-place sort of 9 (odd-even mergesort: 26 CE)
__device__ __forceinline__ void sort9(float p[9]){
    sort4(p[0],p[1],p[2],p[3]);
    ce(p[4],p[5]);
    sort3(p[6],p[7],p[8]);
    { float q[5]; merge23(p[4],p[5],p[6],p[7],p[8],q);
      p[4]=q[0]; p[5]=q[1]; p[6]=q[2]; p[7]=q[3]; p[8]=q[4]; }
    float s[9]; merge45(p[0],p[1],p[2],p[3],p[4],p[5],p[6],p[7],p[8],s);
#pragma unroll
    for(int i=0;i<9;i++) p[i]=s[i];
}

// middle outputs z[4..13] of odd-even merge(9,9) of sorted A, B  -> mid[0..9]
__device__ __forceinline__ void merge99_mid(const float A[9], const float B[9], float mid[10]){
    float v[10], w[8];
    merge55(A[0],A[2],A[4],A[6],A[8], B[0],B[2],B[4],B[6],B[8], v);
    merge44(A[1],A[3],A[5],A[7],      B[1],B[3],B[5],B[7],      w);
    mid[0]=fmaxf(w[1],v[2]);                          // z4
    mid[1]=fminf(w[2],v[3]); mid[2]=fmaxf(w[2],v[3]); // z5,z6
    mid[3]=fminf(w[3],v[4]); mid[4]=fmaxf(w[3],v[4]); // z7,z8
    mid[5]=fminf(w[4],v[5]); mid[6]=fmaxf(w[4],v[5]); // z9,z10
    mid[7]=fminf(w[5],v[6]); mid[8]=fmaxf(w[5],v[6]); // z11,z12
    mid[9]=fminf(w[6],v[7]);                          // z13
}

// rank-13 (0-based) of 27 = 14th smallest of sorted-18 (mid=z[4..13]) u sorted-9 C
__device__ __forceinline__ float select13(const float mid[10], const float C[9]){
    float t0 = fminf(fmaxf(mid[0],C[8]), fmaxf(mid[1],C[7]));
    float t1 = fminf(fmaxf(mid[2],C[6]), fmaxf(mid[3],C[5]));
    float t2 = fminf(fmaxf(mid[4],C[4]), fmaxf(mid[5],C[3]));
    float t3 = fminf(fmaxf(mid[6],C[2]), fmaxf(mid[7],C[1]));
    float t4 = fminf(fmaxf(mid[8],C[0]), mid[9]);
    return fminf(fminf(fminf(t0,t1), fminf(t2,t3)), t4);
}

// ---------------- median kernel (fused diff + mon + median + hist + residual sum) ------
// Proven R8 structure: 1 voxel/thread, 48 regs, TX=32/TY=4/ZC=16, 2304 blocks.
#define TX 32
#define TY 4
#define ZC 16
__global__ __launch_bounds__(TX*TY) void k_median(const float* __restrict__ p){
    __shared__ float sm[2][TY+2][TX+2];
    const int tx = threadIdx.x, ty = threadIdx.y;
    const int tid = ty*TX + tx;
    const int gx0 = blockIdx.x*TX;
    const int gy0 = blockIdx.y*TY;
    const int z0  = blockIdx.z*ZC;

    // ---- fused first-slice key staging + histogram (first 192 blocks) ----
    {
        int b = blockIdx.x + 6*(blockIdx.y + 48*blockIdx.z);
        if (b < 192){
            int i = b*128 + tid;                       // covers N0 exactly
            unsigned key = f2key(p[(size_t)i * WP]);
            g_z0[i] = key;
            atomicAdd(&g_hist[key >> 22], 1);
        }
    }

    // stage one z-plane of d (reflect in y,x) into smem buffer `buf`
    auto load_plane = [&](int z, int buf){
        const int zr = refl(z, DD);
        const float* base = p + (size_t)zr * HH * WP;
        {
            int idx = tid;
            int yy = idx/(TX+2), xx = idx%(TX+2);
            int gy = refl(gy0-1+yy, HH);
            int gx = refl(gx0-1+xx, WW);
            const float* r = base + (size_t)gy*WP + gx;
            sm[buf][yy][xx] = r[1] - r[0];
        }
        {
            int idx = tid + TX*TY;
            if (idx < (TY+2)*(TX+2)){
                int yy = idx/(TX+2), xx = idx%(TX+2);
                int gy = refl(gy0-1+yy, HH);
                int gx = refl(gx0-1+xx, WW);
                const float* r = base + (size_t)gy*WP + gx;
                sm[buf][yy][xx] = r[1] - r[0];
            }
        }
    };
    auto read9 = [&](int buf, float q[9], float& ctr){
#pragma unroll
        for(int j=0;j<9;j++) q[j] = sm[buf][ty + j/3][tx + j%3];
        ctr = q[4];
    };

    float P0[9], P1[9], M0[10], M1[10];
    float c0, c1, dum;

    // prologue: plane z0-1 -> P1 (sorted), plane z0 -> P0 (sorted) + center
    load_plane(z0-1, 0); __syncthreads(); read9(0, P1, dum); sort9(P1);
    load_plane(z0,   1); __syncthreads(); read9(1, P0, c0);  sort9(P0);
    merge99_mid(P1, P0, M0);

    float lsum = 0.0f, lmax = 0.0f;
#pragma unroll 1
    for(int zi = 0; zi < ZC; zi += 2){
        const int z = z0 + zi;
        // window {z-1,z,z+1}: AB=M0=merge(z-1,z); C=plane z+1
        load_plane(z+1, 0); __syncthreads(); read9(0, P1, c1); sort9(P1);
        {
            float med  = select13(M0, P1);
            float diff = c0 - med;
            lsum += diff*diff;
            lmax  = fmaxf(lmax, 1.0f - c0);
        }
        merge99_mid(P0, P1, M1);

        // window {z,z+1,z+2}
        load_plane(z+2, 1); __syncthreads(); read9(1, P0, c0); sort9(P0);
        {
            float med  = select13(M1, P0);
            float diff = c1 - med;
            lsum += diff*diff;
            lmax  = fmaxf(lmax, 1.0f - c1);
        }
        merge99_mid(P1, P0, M0);
    }

    // block reduction
#pragma unroll
    for(int off = 16; off; off >>= 1){
        lsum += __shfl_xor_sync(0xffffffffu, lsum, off);
        lmax  = fmaxf(lmax, __shfl_xor_sync(0xffffffffu, lmax, off));
    }
    __shared__ float rs[TY], rm[TY];
    if ((tid & 31) == 0){ rs[tid>>5] = lsum; rm[tid>>5] = lmax; }
    __syncthreads();
    if (tid == 0){
        float s = rs[0]+rs[1]+rs[2]+rs[3];
        float m = fmaxf(fmaxf(rm[0], rm[1]), fmaxf(rm[2], rm[3]));
        atomicAdd(&g_sum, (double)s);
        atomicMax(&g_mon, __float_as_uint(m));   // m >= 0 always (lmax init 0)
    }
}

// ---------------- scan + gather + select + finalize + reset (single block) --------------
__global__ void k_post(float* __restrict__ out){
    __shared__ int wsum[32];
    __shared__ int sb[2];
    const int t    = threadIdx.x;          // 0..1023
    const int lane = t & 31;
    const int wrp  = t >> 5;

    // warp-level inclusive scan of the 1024-bin histogram
    int h = g_hist[t];
    int v = h;
#pragma unroll
    for (int off = 1; off < 32; off <<= 1){
        int u = __shfl_up_sync(0xffffffffu, v, off);
        if (lane >= off) v += u;
    }
    if (lane == 31) wsum[wrp] = v;
    __syncthreads();
    if (wrp == 0){
        int s = wsum[lane];
#pragma unroll
        for (int off = 1; off < 32; off <<= 1){
            int u = __shfl_up_sync(0xffffffffu, s, off);
            if (lane >= off) s += u;
        }
        wsum[lane] = s;
    }
    __syncthreads();
    int incl = v + (wrp ? wsum[wrp-1] : 0);
    int excl = incl - h;
    if (excl <= RANK && RANK < incl){ sb[0] = t; sb[1] = RANK - excl; }
    __syncthreads();
    const int bkt = sb[0];

    for (int i = t; i < N0; i += 1024){
        unsigned key = g_z0[i];
        if ((int)(key >> 22) == bkt){
            int pos = atomicAdd(&g_ccount, 1);
            g_cand[pos] = key;
        }
    }
    __syncthreads();
    const int m = g_ccount;
    const int r = sb[1];
    for (int i = t; i < m; i += 1024){
        unsigned ki = g_cand[i];
        int less = 0, eq = 0;
        for (int j = 0; j < m; j++){
            unsigned kj = g_cand[j];
            less += (kj < ki);
            eq   += (kj == ki);
        }
        if (less <= r && r < less + eq){
            float val = key2f(ki);
            out[2] = val*val;                     // loss_average
        }
    }
    __syncthreads();
    if (t == 0){
        out[0] = (float)(g_sum * (1.0/(double)TOTD));  // loss_smooth
        out[1] = __uint_as_float(g_mon);               // loss_mon
        g_sum = 0.0; g_mon = 0u; g_ccount = 0;         // reset for next replay
    }
    g_hist[t] = 0;
}

// ---------------- launch ----------------
extern "C" void kernel_launch(void* const* d_in, const int* in_sizes, int n_in,
                              void* d_out, int out_size) {
    const float* p = (const float*)d_in[0];
    float* out = (float*)d_out;

    {
        dim3 grid(WW/TX, HH/TY, DD/ZC);   // 6 x 48 x 8 = 2304 blocks
        dim3 block(TX, TY);
        k_median<<<grid, block>>>(p);
    }
    k_post<<<1, 1024>>>(out);
}

// round 13
// speedup vs baseline: 1.2674x; 1.0024x over previous
#include <cuda_runtime.h>
#include <cuda_bf16.h>
#include <stdint.h>

// ---------------- problem constants (fixed shapes) ----------------
#define DD   128
#define HH   192
#define WP   193            // pred_z last-dim
#define WW   192            // d last-dim (WP-1)
#define TOTD (DD*HH*WW)     // 4,718,592
#define N0   (DD*HH)        // 24,576 first-slice elements
#define RANK ((N0-1)/2)     // 12,287 (lower median, 0-based)
#define NBIN 4096           // radix bins (top 12 bits of sortable key)

// ---------------- device scratch (no allocations allowed) ----------------
__device__ double   g_sum;              // sum of (d-med)^2
__device__ unsigned g_mon;              // float bits of max(relu(1-dz))
__device__ int      g_hist[NBIN];       // radix histogram (top 12 bits of key)
__device__ unsigned g_z0[N0];           // staged sortable keys of first-slice values
__device__ unsigned g_cand[N0];         // candidate keys
__device__ int      g_ccount;

// ---------------- helpers ----------------
__device__ __forceinline__ int refl(int i, int n) {
    return (i < 0) ? -i : ((i >= n) ? (2*n - 2 - i) : i);
}

__device__ __forceinline__ unsigned f2key(float f) {
    unsigned u = __float_as_uint(f);
    return (u & 0x80000000u) ? ~u : (u | 0x80000000u);
}
__device__ __forceinline__ float key2f(unsigned k) {
    unsigned u = (k & 0x80000000u) ? (k & 0x7fffffffu) : ~k;
    return __uint_as_float(u);
}

__device__ __forceinline__ void ce(float& a, float& b) {
    float mn = fminf(a, b);
    float mx = fmaxf(a, b);
    a = mn; b = mx;
}

// ---------- sorting / merging networks (Batcher odd-even) ----------
__device__ __forceinline__ void sort3(float&a,float&b,float&c){ ce(a,b); ce(a,c); ce(b,c); }
__device__ __forceinline__ void sort4(float&a,float&b,float&c,float&d){
    ce(a,b); ce(c,d); ce(a,c); ce(b,d); ce(b,c);
}
__device__ __forceinline__ void merge12(float a0,float b0,float b1,float z[3]){
    float v0=fminf(a0,b0), v1=fmaxf(a0,b0);
    z[0]=v0; z[1]=fminf(b1,v1); z[2]=fmaxf(b1,v1);
}
__device__ __forceinline__ void merge22(float a0,float a1,float b0,float b1,float z[4]){
    float v0=fminf(a0,b0), v1=fmaxf(a0,b0);
    float w0=fminf(a1,b1), w1=fmaxf(a1,b1);
    z[0]=v0; z[1]=fminf(w0,v1); z[2]=fmaxf(w0,v1); z[3]=w1;
}
__device__ __forceinline__ void merge23(float a0,float a1,float b0,float b1,float b2,float z[5]){
    float v[3]; merge12(a0,b0,b2,v);
    float w0=fminf(a1,b1), w1=fmaxf(a1,b1);
    z[0]=v[0];
    z[1]=fminf(w0,v[1]); z[2]=fmaxf(w0,v[1]);
    z[3]=fminf(w1,v[2]); z[4]=fmaxf(w1,v[2]);
}
__device__ __forceinline__ void merge33(float a0,float a1,float a2,float b0,float b1,float b2,float z[6]){
    float v[4]; merge22(a0,a2,b0,b2,v);
    float w0=fminf(a1,b1), w1=fmaxf(a1,b1);
    z[0]=v[0];
    z[1]=fminf(w0,v[1]); z[2]=fmaxf(w0,v[1]);
    z[3]=fminf(w1,v[2]); z[4]=fmaxf(w1,v[2]);
    z[5]=v[3];
}
__device__ __forceinline__ void merge44(float a0,float a1,float a2,float a3,
                                        float b0,float b1,float b2,float b3,float z[8]){
    float v[4]; merge22(a0,a2,b0,b2,v);
    float w[4]; merge22(a1,a3,b1,b3,w);
    z[0]=v[0];
    z[1]=fminf(w[0],v[1]); z[2]=fmaxf(w[0],v[1]);
    z[3]=fminf(w[1],v[2]); z[4]=fmaxf(w[1],v[2]);
    z[5]=fminf(w[2],v[3]); z[6]=fmaxf(w[2],v[3]);
    z[7]=w[3];
}
__device__ __forceinline__ void merge45(float a0,float a1,float a2,float a3,
                                        float b0,float b1,float b2,float b3,float b4,float z[9]){
    float v[5]; merge23(a0,a2,b0,b2,b4,v);
    float w[4]; merge22(a1,a3,b1,b3,w);
    z[0]=v[0];
    z[1]=fminf(w[0],v[1]); z[2]=fmaxf(w[0],v[1]);
    z[3]=fminf(w[1],v[2]); z[4]=fmaxf(w[1],v[2]);
    z[5]=fminf(w[2],v[3]); z[6]=fmaxf(w[2],v[3]);
    z[7]=fminf(w[3],v[4]); z[8]=fmaxf(w[3],v[4]);
}
__device__ __forceinline__ void merge55(float a0,float a1,float a2,float a3,float a4,
                                        float b0,float b1,float b2,float b3,float b4,float z[10]){
    float v[6]; merge33(a0,a2,a4,b0,b2,b4,v);
    float w[4]; merge22(a1,a3,b1,b3,w);
    z[0]=v[0];
    z[1]=fminf(w[0],v[1]); z[2]=fmaxf(w[0],v[1]);
    z[3]=fminf(w[1],v[2]); z[4]=fmaxf(w[1],v[2]);
    z[5]=fminf(w[2],v[3]); z[6]=fmaxf(w[2],v[3]);
    z[7]=fminf(w[3],v[4]); z[8]=fmaxf(w[3],v[4]);
    z[9]=v[5];
}

// in-place sort of 9 (odd-even mergesort: 26 CE)
__device__ __forceinline__ void sort9(float p[9]){
    sort4(p[0],p[1],p[2],p[3]);
    ce(p[4],p[5]);
    sort3(p[6],p[7],p[8]);
    { float q[5]; merge23(p[4],p[5],p[6],p[7],p[8],q);
      p[4]=q[0]; p[5]=q[1]; p[6]=q[2]; p[7]=q[3]; p[8]=q[4]; }
    float s[9]; merge45(p[0],p[1],p[2],p[3],p[4],p[5],p[6],p[7],p[8],s);
#pragma unroll
    for(int i=0;i<9;i++) p[i]=s[i];
}

// middle outputs z[4..13] of odd-even merge(9,9) of sorted A, B  -> mid[0..9]
__device__ __forceinline__ void merge99_mid(const float A[9], const float B[9], float mid[10]){
    float v[10], w[8];
    merge55(A[0],A[2],A[4],A[6],A[8], B[0],B[2],B[4],B[6],B[8], v);
    merge44(A[1],A[3],A[5],A[7],      B[1],B[3],B[5],B[7],      w);
    mid[0]=fmaxf(w[1],v[2]);                          // z4
    mid[1]=fminf(w[2],v[3]); mid[2]=fmaxf(w[2],v[3]); // z5,z6
    mid[3]=fminf(w[3],v[4]); mid[4]=fmaxf(w[3],v[4]); // z7,z8
    mid[5]=fminf(w[4],v[5]); mid[6]=fmaxf(w[4],v[5]); // z9,z10
    mid[7]=fminf(w[5],v[6]); mid[8]=fmaxf(w[5],v[6]); // z11,z12
    mid[9]=fminf(w[6],v[7]);                          // z13
}

// rank-13 (0-based) of 27 = 14th smallest of sorted-18 (mid=z[4..13]) u sorted-9 C
__device__ __forceinline__ float select13(const float mid[10], const float C[9]){
    float t0 = fminf(fmaxf(mid[0],C[8]), fmaxf(mid[1],C[7]));
    float t1 = fminf(fmaxf(mid[2],C[6]), fmaxf(mid[3],C[5]));
    float t2 = fminf(fmaxf(mid[4],C[4]), fmaxf(mid[5],C[3]));
    float t3 = fminf(fmaxf(mid[6],C[2]), fmaxf(mid[7],C[1]));
    float t4 = fminf(fmaxf(mid[8],C[0]), mid[9]);
    return fminf(fminf(fminf(t0,t1), fminf(t2,t3)), t4);
}

// ---------------- median kernel (fused diff + mon + median + hist + residual sum) ------
// Proven R8 structure: 1 voxel/thread, 48 regs, TX=32/TY=4/ZC=16, 2304 blocks.
#define TX 32
#define TY 4
#define ZC 16
__global__ __launch_bounds__(TX*TY) void k_median(const float* __restrict__ p){
    __shared__ float sm[2][TY+2][TX+2];
    const int tx = threadIdx.x, ty = threadIdx.y;
    const int tid = ty*TX + tx;
    const int gx0 = blockIdx.x*TX;
    const int gy0 = blockIdx.y*TY;
    const int z0  = blockIdx.z*ZC;

    // ---- fused first-slice key staging + histogram (first 192 blocks) ----
    {
        int b = blockIdx.x + 6*(blockIdx.y + 48*blockIdx.z);
        if (b < 192){
            int i = b*128 + tid;                       // covers N0 exactly
            unsigned key = f2key(p[(size_t)i * WP]);
            g_z0[i] = key;
            atomicAdd(&g_hist[key >> 20], 1);          // 12-bit radix
        }
    }

    // stage one z-plane of d (reflect in y,x) into smem buffer `buf`
    auto load_plane = [&](int z, int buf){
        const int zr = refl(z, DD);
        const float* base = p + (size_t)zr * HH * WP;
        {
            int idx = tid;
            int yy = idx/(TX+2), xx = idx%(TX+2);
            int gy = refl(gy0-1+yy, HH);
            int gx = refl(gx0-1+xx, WW);
            const float* r = base + (size_t)gy*WP + gx;
            sm[buf][yy][xx] = r[1] - r[0];
        }
        {
            int idx = tid + TX*TY;
            if (idx < (TY+2)*(TX+2)){
                int yy = idx/(TX+2), xx = idx%(TX+2);
                int gy = refl(gy0-1+yy, HH);
                int gx = refl(gx0-1+xx, WW);
                const float* r = base + (size_t)gy*WP + gx;
                sm[buf][yy][xx] = r[1] - r[0];
            }
        }
    };
    auto read9 = [&](int buf, float q[9], float& ctr){
#pragma unroll
        for(int j=0;j<9;j++) q[j] = sm[buf][ty + j/3][tx + j%3];
        ctr = q[4];
    };

    float P0[9], P1[9], M0[10], M1[10];
    float c0, c1, dum;

    // prologue: plane z0-1 -> P1 (sorted), plane z0 -> P0 (sorted) + center
    load_plane(z0-1, 0); __syncthreads(); read9(0, P1, dum); sort9(P1);
    load_plane(z0,   1); __syncthreads(); read9(1, P0, c0);  sort9(P0);
    merge99_mid(P1, P0, M0);

    float lsum = 0.0f, lmax = 0.0f;
#pragma unroll 1
    for(int zi = 0; zi < ZC; zi += 2){
        const int z = z0 + zi;
        // window {z-1,z,z+1}: AB=M0=merge(z-1,z); C=plane z+1
        load_plane(z+1, 0); __syncthreads(); read9(0, P1, c1); sort9(P1);
        {
            float med  = select13(M0, P1);
            float diff = c0 - med;
            lsum += diff*diff;
            lmax  = fmaxf(lmax, 1.0f - c0);
        }
        merge99_mid(P0, P1, M1);

        // window {z,z+1,z+2}
        load_plane(z+2, 1); __syncthreads(); read9(1, P0, c0); sort9(P0);
        {
            float med  = select13(M1, P0);
            float diff = c1 - med;
            lsum += diff*diff;
            lmax  = fmaxf(lmax, 1.0f - c1);
        }
        merge99_mid(P1, P0, M0);
    }

    // block reduction
#pragma unroll
    for(int off = 16; off; off >>= 1){
        lsum += __shfl_xor_sync(0xffffffffu, lsum, off);
        lmax  = fmaxf(lmax, __shfl_xor_sync(0xffffffffu, lmax, off));
    }
    __shared__ float rs[TY], rm[TY];
    if ((tid & 31) == 0){ rs[tid>>5] = lsum; rm[tid>>5] = lmax; }
    __syncthreads();
    if (tid == 0){
        float s = rs[0]+rs[1]+rs[2]+rs[3];
        float m = fmaxf(fmaxf(rm[0], rm[1]), fmaxf(rm[2], rm[3]));
        atomicAdd(&g_sum, (double)s);
        atomicMax(&g_mon, __float_as_uint(m));   // m >= 0 always (lmax init 0)
    }
}

// ---------------- scan + gather + select + finalize + reset (single block) --------------
__global__ void k_post(float* __restrict__ out){
    __shared__ int wsum[32];
    __shared__ int sb[2];
    const int t    = threadIdx.x;          // 0..1023
    const int lane = t & 31;
    const int wrp  = t >> 5;

    // each thread owns 4 consecutive bins; block-wide scan over thread sums
    int h0 = g_hist[4*t+0], h1 = g_hist[4*t+1], h2 = g_hist[4*t+2], h3 = g_hist[4*t+3];
    int local = h0 + h1 + h2 + h3;
    int v = local;
#pragma unroll
    for (int off = 1; off < 32; off <<= 1){
        int u = __shfl_up_sync(0xffffffffu, v, off);
        if (lane >= off) v += u;
    }
    if (lane == 31) wsum[wrp] = v;
    __syncthreads();
    if (wrp == 0){
        int s = wsum[lane];
#pragma unroll
        for (int off = 1; off < 32; off <<= 1){
            int u = __shfl_up_sync(0xffffffffu, s, off);
            if (lane >= off) s += u;
        }
        wsum[lane] = s;
    }
    __syncthreads();
    int excl = v - local + (wrp ? wsum[wrp-1] : 0);   // exclusive prefix of bin 4t
    // walk the 4 owned bins to find the one containing RANK
    int e0 = excl, e1 = e0 + h0, e2 = e1 + h1, e3 = e2 + h2, e4 = e3 + h3;
    if (e0 <= RANK && RANK < e1){ sb[0] = 4*t+0; sb[1] = RANK - e0; }
    if (e1 <= RANK && RANK < e2){ sb[0] = 4*t+1; sb[1] = RANK - e1; }
    if (e2 <= RANK && RANK < e3){ sb[0] = 4*t+2; sb[1] = RANK - e2; }
    if (e3 <= RANK && RANK < e4){ sb[0] = 4*t+3; sb[1] = RANK - e3; }
    __syncthreads();
    const int bkt = sb[0];

    for (int i = t; i < N0; i += 1024){
        unsigned key = g_z0[i];
        if ((int)(key >> 20) == bkt){
            int pos = atomicAdd(&g_ccount, 1);
            g_cand[pos] = key;
        }
    }
    __syncthreads();
    const int m = g_ccount;
    const int r = sb[1];
    for (int i = t; i < m; i += 1024){
        unsigned ki = g_cand[i];
        int less = 0, eq = 0;
        for (int j = 0; j < m; j++){
            unsigned kj = g_cand[j];
            less += (kj < ki);
            eq   += (kj == ki);
        }
        if (less <= r && r < less + eq){
            float val = key2f(ki);
            out[2] = val*val;                     // loss_average
        }
    }
    __syncthreads();
    if (t == 0){
        out[0] = (float)(g_sum * (1.0/(double)TOTD));  // loss_smooth
        out[1] = __uint_as_float(g_mon);               // loss_mon
        g_sum = 0.0; g_mon = 0u; g_ccount = 0;         // reset for next replay
    }
    g_hist[4*t+0] = 0; g_hist[4*t+1] = 0; g_hist[4*t+2] = 0; g_hist[4*t+3] = 0;
}

// ---------------- launch ----------------
extern "C" void kernel_launch(void* const* d_in, const int* in_sizes, int n_in,
                              void* d_out, int out_size) {
    const float* p = (const float*)d_in[0];
    float* out = (float*)d_out;

    {
        dim3 grid(WW/TX, HH/TY, DD/ZC);   // 6 x 48 x 8 = 2304 blocks
        dim3 block(TX, TY);
        k_median<<<grid, block>>>(p);
    }
    k_post<<<1, 1024>>>(out);
}

// round 14
// speedup vs baseline: 1.5647x; 1.2346x over previous
#include <cuda_runtime.h>
#include <cuda_bf16.h>
#include <stdint.h>

// ---------------- problem constants (fixed shapes) ----------------
#define DD   128
#define HH   192
#define WP   193            // pred_z last-dim
#define WW   192            // d last-dim (WP-1)
#define TOTD (DD*HH*WW)     // 4,718,592
#define N0   (DD*HH)        // 24,576 first-slice elements
#define RANK ((N0-1)/2)     // 12,287 (lower median, 0-based)
#define NBIN 4096           // radix bins (top 12 bits of sortable key)

// ---------------- device scratch (no allocations allowed) ----------------
__device__ double   g_sum;              // sum of (d-med)^2
__device__ unsigned g_mon;              // float bits of max(relu(1-dz))
__device__ int      g_hist[NBIN];       // radix histogram (top 12 bits of key)
__device__ unsigned g_z0[N0];           // staged sortable keys of first-slice values
__device__ unsigned g_cand[N0];         // candidate keys
__device__ int      g_ccount;

// ---------------- helpers ----------------
__device__ __forceinline__ int refl(int i, int n) {
    return (i < 0) ? -i : ((i >= n) ? (2*n - 2 - i) : i);
}

__device__ __forceinline__ unsigned f2key(float f) {
    unsigned u = __float_as_uint(f);
    return (u & 0x80000000u) ? ~u : (u | 0x80000000u);
}
__device__ __forceinline__ float key2f(unsigned k) {
    unsigned u = (k & 0x80000000u) ? (k & 0x7fffffffu) : ~k;
    return __uint_as_float(u);
}

__device__ __forceinline__ void ce(float& a, float& b) {
    float mn = fminf(a, b);
    float mx = fmaxf(a, b);
    a = mn; b = mx;
}

// ---------- sorting / merging networks (Batcher odd-even) ----------
__device__ __forceinline__ void sort3(float&a,float&b,float&c){ ce(a,b); ce(a,c); ce(b,c); }
__device__ __forceinline__ void sort4(float&a,float&b,float&c,float&d){
    ce(a,b); ce(c,d); ce(a,c); ce(b,d); ce(b,c);
}
__device__ __forceinline__ void merge12(float a0,float b0,float b1,float z[3]){
    float v0=fminf(a0,b0), v1=fmaxf(a0,b0);
    z[0]=v0; z[1]=fminf(b1,v1); z[2]=fmaxf(b1,v1);
}
__device__ __forceinline__ void merge22(float a0,float a1,float b0,float b1,float z[4]){
    float v0=fminf(a0,b0), v1=fmaxf(a0,b0);
    float w0=fminf(a1,b1), w1=fmaxf(a1,b1);
    z[0]=v0; z[1]=fminf(w0,v1); z[2]=fmaxf(w0,v1); z[3]=w1;
}
__device__ __forceinline__ void merge23(float a0,float a1,float b0,float b1,float b2,float z[5]){
    float v[3]; merge12(a0,b0,b2,v);
    float w0=fminf(a1,b1), w1=fmaxf(a1,b1);
    z[0]=v[0];
    z[1]=fminf(w0,v[1]); z[2]=fmaxf(w0,v[1]);
    z[3]=fminf(w1,v[2]); z[4]=fmaxf(w1,v[2]);
}
__device__ __forceinline__ void merge33(float a0,float a1,float a2,float b0,float b1,float b2,float z[6]){
    float v[4]; merge22(a0,a2,b0,b2,v);
    float w0=fminf(a1,b1), w1=fmaxf(a1,b1);
    z[0]=v[0];
    z[1]=fminf(w0,v[1]); z[2]=fmaxf(w0,v[1]);
    z[3]=fminf(w1,v[2]); z[4]=fmaxf(w1,v[2]);
    z[5]=v[3];
}
__device__ __forceinline__ void merge44(float a0,float a1,float a2,float a3,
                                        float b0,float b1,float b2,float b3,float z[8]){
    float v[4]; merge22(a0,a2,b0,b2,v);
    float w[4]; merge22(a1,a3,b1,b3,w);
    z[0]=v[0];
    z[1]=fminf(w[0],v[1]); z[2]=fmaxf(w[0],v[1]);
    z[3]=fminf(w[1],v[2]); z[4]=fmaxf(w[1],v[2]);
    z[5]=fminf(w[2],v[3]); z[6]=fmaxf(w[2],v[3]);
    z[7]=w[3];
}
__device__ __forceinline__ void merge45(float a0,float a1,float a2,float a3,
                                        float b0,float b1,float b2,float b3,float b4,float z[9]){
    float v[5]; merge23(a0,a2,b0,b2,b4,v);
    float w[4]; merge22(a1,a3,b1,b3,w);
    z[0]=v[0];
    z[1]=fminf(w[0],v[1]); z[2]=fmaxf(w[0],v[1]);
    z[3]=fminf(w[1],v[2]); z[4]=fmaxf(w[1],v[2]);
    z[5]=fminf(w[2],v[3]); z[6]=fmaxf(w[2],v[3]);
    z[7]=fminf(w[3],v[4]); z[8]=fmaxf(w[3],v[4]);
}
__device__ __forceinline__ void merge55(float a0,float a1,float a2,float a3,float a4,
                                        float b0,float b1,float b2,float b3,float b4,float z[10]){
    float v[6]; merge33(a0,a2,a4,b0,b2,b4,v);
    float w[4]; merge22(a1,a3,b1,b3,w);
    z[0]=v[0];
    z[1]=fminf(w[0],v[1]); z[2]=fmaxf(w[0],v[1]);
    z[3]=fminf(w[1],v[2]); z[4]=fmaxf(w[1],v[2]);
    z[5]=fminf(w[2],v[3]); z[6]=fmaxf(w[2],v[3]);
    z[7]=fminf(w[3],v[4]); z[8]=fmaxf(w[3],v[4]);
    z[9]=v[5];
}

// in-place sort of 9 (odd-even mergesort: 26 CE)
__device__ __forceinline__ void sort9(float p[9]){
    sort4(p[0],p[1],p[2],p[3]);
    ce(p[4],p[5]);
    sort3(p[6],p[7],p[8]);
    { float q[5]; merge23(p[4],p[5],p[6],p[7],p[8],q);
      p[4]=q[0]; p[5]=q[1]; p[6]=q[2]; p[7]=q[3]; p[8]=q[4]; }
    float s[9]; merge45(p[0],p[1],p[2],p[3],p[4],p[5],p[6],p[7],p[8],s);
#pragma unroll
    for(int i=0;i<9;i++) p[i]=s[i];
}

// middle outputs z[4..13] of odd-even merge(9,9) of sorted A, B  -> mid[0..9]
__device__ __forceinline__ void merge99_mid(const float A[9], const float B[9], float mid[10]){
    float v[10], w[8];
    merge55(A[0],A[2],A[4],A[6],A[8], B[0],B[2],B[4],B[6],B[8], v);
    merge44(A[1],A[3],A[5],A[7],      B[1],B[3],B[5],B[7],      w);
    mid[0]=fmaxf(w[1],v[2]);                          // z4
    mid[1]=fminf(w[2],v[3]); mid[2]=fmaxf(w[2],v[3]); // z5,z6
    mid[3]=fminf(w[3],v[4]); mid[4]=fmaxf(w[3],v[4]); // z7,z8
    mid[5]=fminf(w[4],v[5]); mid[6]=fmaxf(w[4],v[5]); // z9,z10
    mid[7]=fminf(w[5],v[6]); mid[8]=fmaxf(w[5],v[6]); // z11,z12
    mid[9]=fminf(w[6],v[7]);                          // z13
}

// rank-13 (0-based) of 27 = 14th smallest of sorted-18 (mid=z[4..13]) u sorted-9 C
// symmetric in WHICH two planes were merged; C is the remaining plane.
__device__ __forceinline__ float select13(const float mid[10], const float C[9]){
    float t0 = fminf(fmaxf(mid[0],C[8]), fmaxf(mid[1],C[7]));
    float t1 = fminf(fmaxf(mid[2],C[6]), fmaxf(mid[3],C[5]));
    float t2 = fminf(fmaxf(mid[4],C[4]), fmaxf(mid[5],C[3]));
    float t3 = fminf(fmaxf(mid[6],C[2]), fmaxf(mid[7],C[1]));
    float t4 = fminf(fmaxf(mid[8],C[0]), mid[9]);
    return fminf(fminf(fminf(t0,t1), fminf(t2,t3)), t4);
}

// ---------------- median kernel (fused diff + mon + median + hist + residual sum) ------
// Shared-merge scheme: one merge99_mid serves TWO consecutive windows:
//   window z   = select13(merge(z,z+1), sorted(z-1))
//   window z+1 = select13(merge(z,z+1), sorted(z+2))
#define TX 32
#define TY 4
#define ZC 16
__global__ __launch_bounds__(TX*TY) void k_median(const float* __restrict__ p){
    __shared__ float sm[2][TY+2][TX+2];
    const int tx = threadIdx.x, ty = threadIdx.y;
    const int tid = ty*TX + tx;
    const int gx0 = blockIdx.x*TX;
    const int gy0 = blockIdx.y*TY;
    const int z0  = blockIdx.z*ZC;

    // ---- fused first-slice key staging + histogram (first 192 blocks) ----
    {
        int b = blockIdx.x + 6*(blockIdx.y + 48*blockIdx.z);
        if (b < 192){
            int i = b*128 + tid;                       // covers N0 exactly
            unsigned key = f2key(p[(size_t)i * WP]);
            g_z0[i] = key;
            atomicAdd(&g_hist[key >> 20], 1);          // 12-bit radix
        }
    }

    // stage one z-plane of d (reflect in y,x) into smem buffer `buf`
    auto load_plane = [&](int z, int buf){
        const int zr = refl(z, DD);
        const float* base = p + (size_t)zr * HH * WP;
        {
            int idx = tid;
            int yy = idx/(TX+2), xx = idx%(TX+2);
            int gy = refl(gy0-1+yy, HH);
            int gx = refl(gx0-1+xx, WW);
            const float* r = base + (size_t)gy*WP + gx;
            sm[buf][yy][xx] = r[1] - r[0];
        }
        {
            int idx = tid + TX*TY;
            if (idx < (TY+2)*(TX+2)){
                int yy = idx/(TX+2), xx = idx%(TX+2);
                int gy = refl(gy0-1+yy, HH);
                int gx = refl(gx0-1+xx, WW);
                const float* r = base + (size_t)gy*WP + gx;
                sm[buf][yy][xx] = r[1] - r[0];
            }
        }
    };
    auto read9 = [&](int buf, float q[9], float& ctr){
#pragma unroll
        for(int j=0;j<9;j++) q[j] = sm[buf][ty + j/3][tx + j%3];
        ctr = q[4];
    };

    float Cm[9], Sk[9], M[10];
    float XA[9], YA[9], XB[9], YB[9], MB[10];
    float c0, c1, dum;
    float lsum = 0.0f, lmax = 0.0f;

    // residual accumulator for one window
    auto acc = [&](float med, float ctr){
        float diff = ctr - med;
        lsum += diff*diff;
        lmax  = fmaxf(lmax, 1.0f - ctr);
    };

    // prologue: state invariant at loop top:
    //   Cm = sorted(z-1), Sk = sorted(z+1), M = merge(z, z+1),
    //   c0 = center(z), c1 = center(z+1); next smem buffer parity = 1
    load_plane(z0-1, 0); __syncthreads(); read9(0, Cm, dum); sort9(Cm);
    load_plane(z0,   1); __syncthreads(); read9(1, XA, c0);  sort9(XA);
    load_plane(z0+1, 0); __syncthreads(); read9(0, Sk, c1);  sort9(Sk);
    merge99_mid(XA, Sk, M);

#pragma unroll 1
    for(int zi = 0; zi < ZC; zi += 4){
        const int z = z0 + zi;
        // ---- pair A: windows z, z+1 (shared merge M) ----
        acc(select13(M, Cm), c0);
        load_plane(z+2, 1); __syncthreads(); read9(1, XA, c0); sort9(XA);
        acc(select13(M, XA), c1);
        load_plane(z+3, 0); __syncthreads(); read9(0, YA, c1); sort9(YA);
        merge99_mid(XA, YA, MB);
        // state for pair B: merge = MB, C(z+2)=Sk, C(z+3)=XB (to load), centers c0,c1

        // ---- pair B: windows z+2, z+3 (shared merge MB) ----
        acc(select13(MB, Sk), c0);
        load_plane(z+4, 1); __syncthreads(); read9(1, XB, c0); sort9(XB);
        acc(select13(MB, XB), c1);
        if (zi + 4 < ZC){
            load_plane(z+5, 0); __syncthreads(); read9(0, YB, c1); sort9(YB);
            merge99_mid(XB, YB, M);
            // rotate for next top: Cm = sorted(z+3) = YA, Sk = sorted(z+5) = YB
#pragma unroll
            for(int j=0;j<9;j++){ Cm[j] = YA[j]; Sk[j] = YB[j]; }
        }
    }

    // block reduction
#pragma unroll
    for(int off = 16; off; off >>= 1){
        lsum += __shfl_xor_sync(0xffffffffu, lsum, off);
        lmax  = fmaxf(lmax, __shfl_xor_sync(0xffffffffu, lmax, off));
    }
    __shared__ float rs[TY], rm[TY];
    if ((tid & 31) == 0){ rs[tid>>5] = lsum; rm[tid>>5] = lmax; }
    __syncthreads();
    if (tid == 0){
        float s = rs[0]+rs[1]+rs[2]+rs[3];
        float m = fmaxf(fmaxf(rm[0], rm[1]), fmaxf(rm[2], rm[3]));
        atomicAdd(&g_sum, (double)s);
        atomicMax(&g_mon, __float_as_uint(m));   // m >= 0 always (lmax init 0)
    }
}

// ---------------- scan + gather + select + finalize + reset (single block) --------------
__global__ void k_post(float* __restrict__ out){
    __shared__ int wsum[32];
    __shared__ int sb[2];
    const int t    = threadIdx.x;          // 0..1023
    const int lane = t & 31;
    const int wrp  = t >> 5;

    // each thread owns 4 consecutive bins; block-wide scan over thread sums
    int h0 = g_hist[4*t+0], h1 = g_hist[4*t+1], h2 = g_hist[4*t+2], h3 = g_hist[4*t+3];
    int local = h0 + h1 + h2 + h3;
    int v = local;
#pragma unroll
    for (int off = 1; off < 32; off <<= 1){
        int u = __shfl_up_sync(0xffffffffu, v, off);
        if (lane >= off) v += u;
    }
    if (lane == 31) wsum[wrp] = v;
    __syncthreads();
    if (wrp == 0){
        int s = wsum[lane];
#pragma unroll
        for (int off = 1; off < 32; off <<= 1){
            int u = __shfl_up_sync(0xffffffffu, s, off);
            if (lane >= off) s += u;
        }
        wsum[lane] = s;
    }
    __syncthreads();
    int excl = v - local + (wrp ? wsum[wrp-1] : 0);   // exclusive prefix of bin 4t
    int e0 = excl, e1 = e0 + h0, e2 = e1 + h1, e3 = e2 + h2, e4 = e3 + h3;
    if (e0 <= RANK && RANK < e1){ sb[0] = 4*t+0; sb[1] = RANK - e0; }
    if (e1 <= RANK && RANK < e2){ sb[0] = 4*t+1; sb[1] = RANK - e1; }
    if (e2 <= RANK && RANK < e3){ sb[0] = 4*t+2; sb[1] = RANK - e2; }
    if (e3 <= RANK && RANK < e4){ sb[0] = 4*t+3; sb[1] = RANK - e3; }
    __syncthreads();
    const int bkt = sb[0];

    // gather: fully unrolled (24 iterations) -> all loads in flight at once (MLP)
    unsigned keys[N0/1024];
#pragma unroll
    for (int k = 0; k < N0/1024; k++) keys[k] = g_z0[t + k*1024];
#pragma unroll
    for (int k = 0; k < N0/1024; k++){
        if ((int)(keys[k] >> 20) == bkt){
            int pos = atomicAdd(&g_ccount, 1);
            g_cand[pos] = keys[k];
        }
    }
    __syncthreads();
    const int m = g_ccount;
    const int r = sb[1];
    for (int i = t; i < m; i += 1024){
        unsigned ki = g_cand[i];
        int less = 0, eq = 0;
        for (int j = 0; j < m; j++){
            unsigned kj = g_cand[j];
            less += (kj < ki);
            eq   += (kj == ki);
        }
        if (less <= r && r < less + eq){
            float val = key2f(ki);
            out[2] = val*val;                     // loss_average
        }
    }
    __syncthreads();
    if (t == 0){
        out[0] = (float)(g_sum * (1.0/(double)TOTD));  // loss_smooth
        out[1] = __uint_as_float(g_mon);               // loss_mon
        g_sum = 0.0; g_mon = 0u; g_ccount = 0;         // reset for next replay
    }
    g_hist[4*t+0] = 0; g_hist[4*t+1] = 0; g_hist[4*t+2] = 0; g_hist[4*t+3] = 0;
}

// ---------------- launch ----------------
extern "C" void kernel_launch(void* const* d_in, const int* in_sizes, int n_in,
                              void* d_out, int out_size) {
    const float* p = (const float*)d_in[0];
    float* out = (float*)d_out;

    {
        dim3 grid(WW/TX, HH/TY, DD/ZC);   // 6 x 48 x 8 = 2304 blocks
        dim3 block(TX, TY);
        k_median<<<grid, block>>>(p);
    }
    k_post<<<1, 1024>>>(out);
}